// round 10
// baseline (speedup 1.0000x reference)
#include <cuda_runtime.h>
#include <cuda_bf16.h>
#include <math.h>

// Shapes (fixed by the problem)
#define BATCH 16
#define CHAN  256
#define HH_   224
#define WW_   224
#define PLANE_ELEMS (HH_ * WW_)          // 50176 floats per plane
#define PLANE_V4    (PLANE_ELEMS / 4)    // 12544 float4 per plane
#define NPLANES     (BATCH * CHAN)       // 4096
#define W4_PER_ROW  (WW_ / 4)            // 56 float4 per row
#define SUB_ELEMS   (112 * 112)

// scale blocks: 7 per plane, 7 float4 per thread, 256 threads
#define SBLK_PER_PLANE 7
#define V4_PER_THREAD  7
#define SBLK_V4 (256 * V4_PER_THREAD)        // 1792 float4 per block
#define NSCB_PER_BATCH (CHAN * SBLK_PER_PLANE) // 1792 scale blocks per batch
#define NSUMB NPLANES                        // 4096 sum blocks (1 per plane)
#define TOTALB (NSUMB + BATCH * NSCB_PER_BATCH) // 32768

// Scratch globals (no allocation allowed)
__device__ float    g_sums[NPLANES * 4];
__device__ float    g_scale[NPLANES];
__device__ unsigned g_done[BATCH];       // sum-blocks-completed per batch
__device__ unsigned g_flag[BATCH];       // scale released per batch

__global__ void init_kernel() {
    if (threadIdx.x < BATCH) {
        g_done[threadIdx.x] = 0u;
        g_flag[threadIdx.x] = 0u;
    }
}

// ---------------------------------------------------------------------------
// One kernel, block-ID layout: S0,S1,[C0,S2],[C1,S3],...,[C13,S15],C14,C15
//   S_b = 256 sum blocks for batch b (one plane each)
//   C_b = 1792 scale blocks for batch b
// CTAs are issued in ID order, so every sum block is issued before any scale
// block that depends on it -> spin-wait is deadlock-free.
// ---------------------------------------------------------------------------
__global__ __launch_bounds__(256) void pipeline_kernel(
        const float* __restrict__ x, float* __restrict__ out,
        const float* __restrict__ w1, const float* __restrict__ w2,
        const float* __restrict__ w_enc) {
    const int bid = blockIdx.x;
    const int t = threadIdx.x;

    // ---- decode block role from the interleaved layout ----
    int is_scale, plane = 0, b = 0, inner = 0;
    if (bid < 512) {                       // S0, S1
        is_scale = 0; plane = bid;
    } else if (bid < 512 + 14 * 2048) {    // [C_j (1792), S_{j+2} (256)] x14
        int q = bid - 512;
        int pair = q >> 11;                // /2048
        int r = q & 2047;
        if (r < NSCB_PER_BATCH) { is_scale = 1; b = pair; inner = r; }
        else { is_scale = 0; plane = (pair + 2) * CHAN + (r - NSCB_PER_BATCH); }
    } else {                               // C14, C15
        int q = bid - (512 + 14 * 2048);
        is_scale = 1; b = 14 + q / NSCB_PER_BATCH; inner = q % NSCB_PER_BATCH;
    }

    if (is_scale) {
        // ------------- scale block: out = x * s[plane] -------------
        if (t == 0) {
            while (atomicAdd(&g_flag[b], 0u) == 0u) __nanosleep(128);
        }
        __syncthreads();
        const int pl = b * CHAN + inner / SBLK_PER_PLANE;
        const float s = __ldcg(&g_scale[pl]);
        const size_t base = ((size_t)b * NSCB_PER_BATCH + inner) * SBLK_V4 + t;
        const float4* __restrict__ src = (const float4*)x;
        float4* __restrict__ dst = (float4*)out;
        float4 v[V4_PER_THREAD];
        #pragma unroll
        for (int k = 0; k < V4_PER_THREAD; k++)
            v[k] = src[base + (size_t)k * 256];
        #pragma unroll
        for (int k = 0; k < V4_PER_THREAD; k++) {
            v[k].x *= s; v[k].y *= s; v[k].z *= s; v[k].w *= s;
            __stcs(&dst[base + (size_t)k * 256], v[k]);
        }
        return;
    }

    // ------------- sum block: parity sums for one plane -------------
    b = plane >> 8;
    const float4* __restrict__ p = (const float4*)x + (size_t)plane * PLANE_V4;

    float a0 = 0.f, a1 = 0.f, a2 = 0.f, a3 = 0.f;
    #pragma unroll 7
    for (int i = t; i < PLANE_V4; i += 256) {
        float4 v = p[i];
        int h = i / W4_PER_ROW;
        float ev = v.x + v.z;
        float od = v.y + v.w;
        if (h & 1) { a1 += ev; a3 += od; }
        else       { a0 += ev; a2 += od; }
    }
    #pragma unroll
    for (int off = 16; off > 0; off >>= 1) {
        a0 += __shfl_down_sync(0xffffffffu, a0, off);
        a1 += __shfl_down_sync(0xffffffffu, a1, off);
        a2 += __shfl_down_sync(0xffffffffu, a2, off);
        a3 += __shfl_down_sync(0xffffffffu, a3, off);
    }

    __shared__ float red[8][4];
    __shared__ unsigned s_last;
    int lane = t & 31, wid = t >> 5;
    if (lane == 0) { red[wid][0] = a0; red[wid][1] = a1; red[wid][2] = a2; red[wid][3] = a3; }
    __syncthreads();
    if (t < 4) {
        float acc = 0.f;
        #pragma unroll
        for (int w = 0; w < 8; w++) acc += red[w][t];
        g_sums[(size_t)plane * 4 + t] = acc;
        __threadfence();
    }
    __syncthreads();
    if (t == 0) s_last = atomicAdd(&g_done[b], 1u);
    __syncthreads();
    if (s_last != CHAN - 1) return;

    // ------------- last sum block of batch b: inline head -------------
    __shared__ float ori[4][CHAN];
    __shared__ float ysh[CHAN];
    __shared__ float hsh[CHAN / 2];
    __shared__ float rr[8][4];
    __shared__ int s_top;

    const int c = t;
    const float inv = 0.5f / (float)SUB_ELEMS;
    const size_t gi = ((size_t)b * CHAN + c) * 4;
    float m1 = __ldcg(&g_sums[gi + 0]) * inv;
    float m2 = __ldcg(&g_sums[gi + 1]) * inv;
    float m3 = __ldcg(&g_sums[gi + 2]) * inv;
    float m4 = __ldcg(&g_sums[gi + 3]) * inv;

    float LL  =  m1 + m2 + m3 + m4;
    float HL  = -m1 - m2 + m3 + m4;
    float LH  = -m1 + m2 - m3 + m4;
    float HHb =  m1 - m2 - m3 + m4;
    ori[0][c] = LL; ori[1][c] = HL; ori[2][c] = LH; ori[3][c] = HHb;

    float we = w_enc[c];
    float p0 = LL * we, p1 = HL * we, p2 = LH * we, p3 = HHb * we;
    #pragma unroll
    for (int off = 16; off > 0; off >>= 1) {
        p0 += __shfl_down_sync(0xffffffffu, p0, off);
        p1 += __shfl_down_sync(0xffffffffu, p1, off);
        p2 += __shfl_down_sync(0xffffffffu, p2, off);
        p3 += __shfl_down_sync(0xffffffffu, p3, off);
    }
    if (lane == 0) { rr[wid][0] = p0; rr[wid][1] = p1; rr[wid][2] = p2; rr[wid][3] = p3; }
    __syncthreads();
    if (t == 0) {
        float l0 = 0.f, l1 = 0.f, l2 = 0.f, l3 = 0.f;
        #pragma unroll
        for (int w = 0; w < 8; w++) { l0 += rr[w][0]; l1 += rr[w][1]; l2 += rr[w][2]; l3 += rr[w][3]; }
        int best = 0; float bv = l0;
        if (l1 > bv) { bv = l1; best = 1; }
        if (l2 > bv) { bv = l2; best = 2; }
        if (l3 > bv) { bv = l3; best = 3; }
        s_top = best;
    }
    __syncthreads();

    float Q = ori[s_top][c];
    ysh[c] = fmaxf(LL - Q, 0.f) + fmaxf(HL - Q, 0.f)
           + fmaxf(LH - Q, 0.f) + fmaxf(HHb - Q, 0.f);
    __syncthreads();

    if (c < CHAN / 2) {
        const float* __restrict__ row = w1 + (size_t)c * CHAN;
        float acc = 0.f;
        #pragma unroll 8
        for (int k = 0; k < CHAN; k++) acc = fmaf(ysh[k], row[k], acc);
        hsh[c] = fmaxf(acc, 0.f);
    }
    __syncthreads();

    {
        const float* __restrict__ row = w2 + (size_t)c * (CHAN / 2);
        float acc = 0.f;
        #pragma unroll 8
        for (int k = 0; k < CHAN / 2; k++) acc = fmaf(hsh[k], row[k], acc);
        g_scale[b * CHAN + c] = 1.0f / (1.0f + __expf(-acc));
        __threadfence();
    }
    __syncthreads();
    if (t == 0) atomicExch(&g_flag[b], 1u);
}

// ---------------------------------------------------------------------------
extern "C" void kernel_launch(void* const* d_in, const int* in_sizes, int n_in,
                              void* d_out, int out_size) {
    const float* x     = (const float*)d_in[0];  // [16,256,224,224]
    const float* w1    = (const float*)d_in[1];  // [128,256]
    const float* w2    = (const float*)d_in[2];  // [256,128]
    const float* w_enc = (const float*)d_in[3];  // [1,256]
    float* out = (float*)d_out;

    init_kernel<<<1, 32>>>();
    pipeline_kernel<<<TOTALB, 256>>>(x, out, w1, w2, w_enc);
}

// round 11
// speedup vs baseline: 1.9015x; 1.9015x over previous
#include <cuda_runtime.h>
#include <cuda_bf16.h>
#include <math.h>

// Shapes (fixed by the problem)
#define BATCH 16
#define CHAN  256
#define HH_   224
#define WW_   224
#define PLANE_ELEMS (HH_ * WW_)          // 50176 floats per plane
#define PLANE_V4    (PLANE_ELEMS / 4)    // 12544 float4 per plane
#define NPLANES     (BATCH * CHAN)       // 4096
#define W4_PER_ROW  (WW_ / 4)            // 56 float4 per row
#define SUB_ELEMS   (112 * 112)

// scale kernel tiling: 7 blocks per plane, 7 float4 per thread
#define SBLK_PER_PLANE 7
#define V4_PER_THREAD  7
#define SBLK_V4 (256 * V4_PER_THREAD)          // 1792 float4 per block
#define NSCB_PER_BATCH (CHAN * SBLK_PER_PLANE) // 1792 scale blocks per batch
#define NSCB (BATCH * NSCB_PER_BATCH)          // 28672

// Scratch globals (no allocation allowed)
__device__ float    g_sums[NPLANES * 4];
__device__ float    g_scale[NPLANES];
__device__ unsigned g_done[BATCH];
__device__ unsigned g_flag[BATCH];

__global__ void init_kernel() {
    if (threadIdx.x < BATCH) {
        g_done[threadIdx.x] = 0u;
        g_flag[threadIdx.x] = 0u;
    }
}

// ---------------------------------------------------------------------------
// K1: parity sums (one block per plane) + inline head on the last block of
// each batch. Fires griddepcontrol.launch_dependents at entry so K2's CTAs
// begin launching as soon as all K1 CTAs have launched (i.e., K2 only ever
// uses slots K1 has freed — cannot starve K1).
// ---------------------------------------------------------------------------
__global__ __launch_bounds__(256) void sum_head_kernel(
        const float* __restrict__ x,
        const float* __restrict__ w1, const float* __restrict__ w2,
        const float* __restrict__ w_enc) {
    asm volatile("griddepcontrol.launch_dependents;" ::: "memory");

    const int plane = blockIdx.x;
    const int b = plane >> 8;
    const int t = threadIdx.x;
    const float4* __restrict__ p = (const float4*)x + (size_t)plane * PLANE_V4;

    float a0 = 0.f, a1 = 0.f, a2 = 0.f, a3 = 0.f;
    #pragma unroll 7
    for (int i = t; i < PLANE_V4; i += 256) {
        float4 v = p[i];
        int h = i / W4_PER_ROW;
        float ev = v.x + v.z;
        float od = v.y + v.w;
        if (h & 1) { a1 += ev; a3 += od; }
        else       { a0 += ev; a2 += od; }
    }
    #pragma unroll
    for (int off = 16; off > 0; off >>= 1) {
        a0 += __shfl_down_sync(0xffffffffu, a0, off);
        a1 += __shfl_down_sync(0xffffffffu, a1, off);
        a2 += __shfl_down_sync(0xffffffffu, a2, off);
        a3 += __shfl_down_sync(0xffffffffu, a3, off);
    }

    __shared__ float red[8][4];
    __shared__ unsigned s_last;
    int lane = t & 31, wid = t >> 5;
    if (lane == 0) { red[wid][0] = a0; red[wid][1] = a1; red[wid][2] = a2; red[wid][3] = a3; }
    __syncthreads();
    if (t < 4) {
        float acc = 0.f;
        #pragma unroll
        for (int w = 0; w < 8; w++) acc += red[w][t];
        g_sums[(size_t)plane * 4 + t] = acc;
        __threadfence();
    }
    __syncthreads();
    if (t == 0) s_last = atomicAdd(&g_done[b], 1u);
    __syncthreads();
    if (s_last != CHAN - 1) return;

    // ---- last block of batch b: inline head ----
    __shared__ float ori[4][CHAN];
    __shared__ float ysh[CHAN];
    __shared__ float hsh[CHAN / 2];
    __shared__ float rr[8][4];
    __shared__ int s_top;

    const int c = t;
    const float inv = 0.5f / (float)SUB_ELEMS;
    const size_t gi = ((size_t)b * CHAN + c) * 4;
    float m1 = __ldcg(&g_sums[gi + 0]) * inv;
    float m2 = __ldcg(&g_sums[gi + 1]) * inv;
    float m3 = __ldcg(&g_sums[gi + 2]) * inv;
    float m4 = __ldcg(&g_sums[gi + 3]) * inv;

    float LL  =  m1 + m2 + m3 + m4;
    float HL  = -m1 - m2 + m3 + m4;
    float LH  = -m1 + m2 - m3 + m4;
    float HHb =  m1 - m2 - m3 + m4;
    ori[0][c] = LL; ori[1][c] = HL; ori[2][c] = LH; ori[3][c] = HHb;

    float we = w_enc[c];
    float p0 = LL * we, p1 = HL * we, p2 = LH * we, p3 = HHb * we;
    #pragma unroll
    for (int off = 16; off > 0; off >>= 1) {
        p0 += __shfl_down_sync(0xffffffffu, p0, off);
        p1 += __shfl_down_sync(0xffffffffu, p1, off);
        p2 += __shfl_down_sync(0xffffffffu, p2, off);
        p3 += __shfl_down_sync(0xffffffffu, p3, off);
    }
    if (lane == 0) { rr[wid][0] = p0; rr[wid][1] = p1; rr[wid][2] = p2; rr[wid][3] = p3; }
    __syncthreads();
    if (t == 0) {
        float l0 = 0.f, l1 = 0.f, l2 = 0.f, l3 = 0.f;
        #pragma unroll
        for (int w = 0; w < 8; w++) { l0 += rr[w][0]; l1 += rr[w][1]; l2 += rr[w][2]; l3 += rr[w][3]; }
        int best = 0; float bv = l0;
        if (l1 > bv) { bv = l1; best = 1; }
        if (l2 > bv) { bv = l2; best = 2; }
        if (l3 > bv) { bv = l3; best = 3; }
        s_top = best;
    }
    __syncthreads();

    float Q = ori[s_top][c];
    ysh[c] = fmaxf(LL - Q, 0.f) + fmaxf(HL - Q, 0.f)
           + fmaxf(LH - Q, 0.f) + fmaxf(HHb - Q, 0.f);
    __syncthreads();

    if (c < CHAN / 2) {
        const float* __restrict__ row = w1 + (size_t)c * CHAN;
        float acc = 0.f;
        #pragma unroll 8
        for (int k = 0; k < CHAN; k++) acc = fmaf(ysh[k], row[k], acc);
        hsh[c] = fmaxf(acc, 0.f);
    }
    __syncthreads();

    {
        const float* __restrict__ row = w2 + (size_t)c * (CHAN / 2);
        float acc = 0.f;
        #pragma unroll 8
        for (int k = 0; k < CHAN / 2; k++) acc = fmaf(hsh[k], row[k], acc);
        g_scale[b * CHAN + c] = 1.0f / (1.0f + __expf(-acc));
        __threadfence();
    }
    __syncthreads();
    if (t == 0) atomicExch(&g_flag[b], 1u);
}

// ---------------------------------------------------------------------------
// K2 (PDL secondary): out = x * s. Issues its 7 independent x-loads BEFORE
// the flag wait (x is read-only), so even a briefly-waiting block is doing
// useful DRAM work. Block order ascending by batch matches K1 completion.
// ---------------------------------------------------------------------------
__global__ __launch_bounds__(256) void scale_kernel(const float* __restrict__ x,
                                                    float* __restrict__ out) {
    const int b = blockIdx.x / NSCB_PER_BATCH;
    const int inner = blockIdx.x % NSCB_PER_BATCH;
    const int plane = b * CHAN + inner / SBLK_PER_PLANE;
    const size_t base = (size_t)blockIdx.x * SBLK_V4 + threadIdx.x;

    const float4* __restrict__ src = (const float4*)x;
    float4* __restrict__ dst = (float4*)out;

    float4 v[V4_PER_THREAD];
    #pragma unroll
    for (int k = 0; k < V4_PER_THREAD; k++)
        v[k] = src[base + (size_t)k * 256];

    if (threadIdx.x == 0) {
        while (atomicAdd(&g_flag[b], 0u) == 0u) __nanosleep(64);
    }
    __syncthreads();
    const float s = __ldcg(&g_scale[plane]);

    #pragma unroll
    for (int k = 0; k < V4_PER_THREAD; k++) {
        v[k].x *= s; v[k].y *= s; v[k].z *= s; v[k].w *= s;
        __stcs(&dst[base + (size_t)k * 256], v[k]);
    }
}

// ---------------------------------------------------------------------------
extern "C" void kernel_launch(void* const* d_in, const int* in_sizes, int n_in,
                              void* d_out, int out_size) {
    const float* x     = (const float*)d_in[0];  // [16,256,224,224]
    const float* w1    = (const float*)d_in[1];  // [128,256]
    const float* w2    = (const float*)d_in[2];  // [256,128]
    const float* w_enc = (const float*)d_in[3];  // [1,256]
    float* out = (float*)d_out;

    init_kernel<<<1, 32>>>();
    sum_head_kernel<<<NPLANES, 256>>>(x, w1, w2, w_enc);

    // K2 with programmatic stream serialization (PDL secondary)
    cudaLaunchConfig_t cfg = {};
    cfg.gridDim  = dim3(NSCB, 1, 1);
    cfg.blockDim = dim3(256, 1, 1);
    cfg.dynamicSmemBytes = 0;
    cudaLaunchAttribute attr[1];
    attr[0].id = cudaLaunchAttributeProgrammaticStreamSerialization;
    attr[0].val.programmaticStreamSerializationAllowed = 1;
    cfg.attrs = attr;
    cfg.numAttrs = 1;
    cudaLaunchKernelEx(&cfg, scale_kernel, x, (float*)out);
}

// round 13
// speedup vs baseline: 1.9519x; 1.0265x over previous
#include <cuda_runtime.h>
#include <cuda_bf16.h>
#include <math.h>

// Shapes (fixed by the problem)
#define BATCH 16
#define CHAN  256
#define HH_   224
#define WW_   224
#define PLANE_ELEMS (HH_ * WW_)          // 50176 floats per plane
#define PLANE_V4    (PLANE_ELEMS / 4)    // 12544 float4 per plane
#define NPLANES     (BATCH * CHAN)       // 4096
#define W4_PER_ROW  (WW_ / 4)            // 56 float4 per row
#define SUB_ELEMS   (112 * 112)

// scale kernel tiling: 7 blocks per plane, 7 float4 per thread
#define SBLK_PER_PLANE 7
#define V4_PER_THREAD  7
#define SBLK_V4 (256 * V4_PER_THREAD)          // 1792 float4 per block
#define NSCB_PER_BATCH (CHAN * SBLK_PER_PLANE) // 1792 scale blocks per batch
#define NSCB (BATCH * NSCB_PER_BATCH)          // 28672

// Scratch globals — all counters are MONOTONIC (never reset), so no init
// kernel is needed. Runs are stream-serialized, so per-run phases are clean.
__device__ float    g_sums[NPLANES * 4];
__device__ float    g_scale[NPLANES];
__device__ unsigned g_done[BATCH];   // K1 arrivals per batch (256 per run)
__device__ unsigned g_flag[BATCH];   // head publishes 256*(run+1)
__device__ unsigned g_k2[BATCH];     // K2 arrivals per batch (1792 per run)

// ---------------------------------------------------------------------------
// K1: parity sums (one block per plane) + inline head on the last block of
// each batch. Fires griddepcontrol.launch_dependents at entry so K2 CTAs
// only ever occupy slots K1 has freed — cannot starve K1.
// ---------------------------------------------------------------------------
__global__ __launch_bounds__(256) void sum_head_kernel(
        const float* __restrict__ x,
        const float* __restrict__ w1, const float* __restrict__ w2,
        const float* __restrict__ w_enc) {
    asm volatile("griddepcontrol.launch_dependents;" ::: "memory");

    const int plane = blockIdx.x;
    const int b = plane >> 8;
    const int t = threadIdx.x;
    const float4* __restrict__ p = (const float4*)x + (size_t)plane * PLANE_V4;

    float a0 = 0.f, a1 = 0.f, a2 = 0.f, a3 = 0.f;
    #pragma unroll 7
    for (int i = t; i < PLANE_V4; i += 256) {
        float4 v = p[i];
        int h = i / W4_PER_ROW;
        float ev = v.x + v.z;
        float od = v.y + v.w;
        if (h & 1) { a1 += ev; a3 += od; }
        else       { a0 += ev; a2 += od; }
    }
    #pragma unroll
    for (int off = 16; off > 0; off >>= 1) {
        a0 += __shfl_down_sync(0xffffffffu, a0, off);
        a1 += __shfl_down_sync(0xffffffffu, a1, off);
        a2 += __shfl_down_sync(0xffffffffu, a2, off);
        a3 += __shfl_down_sync(0xffffffffu, a3, off);
    }

    __shared__ float red[8][4];
    __shared__ unsigned s_old;
    int lane = t & 31, wid = t >> 5;
    if (lane == 0) { red[wid][0] = a0; red[wid][1] = a1; red[wid][2] = a2; red[wid][3] = a3; }
    __syncthreads();
    if (t < 4) {
        float acc = 0.f;
        #pragma unroll
        for (int w = 0; w < 8; w++) acc += red[w][t];
        g_sums[(size_t)plane * 4 + t] = acc;
        __threadfence();
    }
    __syncthreads();
    if (t == 0) s_old = atomicAdd(&g_done[b], 1u);
    __syncthreads();
    const unsigned old = s_old;
    if ((old & 255u) != 255u) return;   // not the last block of this batch/run

    // ---- last block of batch b this run: inline head ----
    __shared__ float ori[4][CHAN];
    __shared__ float ysh[CHAN];
    __shared__ float hsh[CHAN / 2];
    __shared__ float rr[8][4];
    __shared__ int s_top;

    const int c = t;
    const float inv = 0.5f / (float)SUB_ELEMS;
    const size_t gi = ((size_t)b * CHAN + c) * 4;
    float m1 = __ldcg(&g_sums[gi + 0]) * inv;
    float m2 = __ldcg(&g_sums[gi + 1]) * inv;
    float m3 = __ldcg(&g_sums[gi + 2]) * inv;
    float m4 = __ldcg(&g_sums[gi + 3]) * inv;

    float LL  =  m1 + m2 + m3 + m4;
    float HL  = -m1 - m2 + m3 + m4;
    float LH  = -m1 + m2 - m3 + m4;
    float HHb =  m1 - m2 - m3 + m4;
    ori[0][c] = LL; ori[1][c] = HL; ori[2][c] = LH; ori[3][c] = HHb;

    float we = w_enc[c];
    float p0 = LL * we, p1 = HL * we, p2 = LH * we, p3 = HHb * we;
    #pragma unroll
    for (int off = 16; off > 0; off >>= 1) {
        p0 += __shfl_down_sync(0xffffffffu, p0, off);
        p1 += __shfl_down_sync(0xffffffffu, p1, off);
        p2 += __shfl_down_sync(0xffffffffu, p2, off);
        p3 += __shfl_down_sync(0xffffffffu, p3, off);
    }
    if (lane == 0) { rr[wid][0] = p0; rr[wid][1] = p1; rr[wid][2] = p2; rr[wid][3] = p3; }
    __syncthreads();
    if (t == 0) {
        float l0 = 0.f, l1 = 0.f, l2 = 0.f, l3 = 0.f;
        #pragma unroll
        for (int w = 0; w < 8; w++) { l0 += rr[w][0]; l1 += rr[w][1]; l2 += rr[w][2]; l3 += rr[w][3]; }
        int best = 0; float bv = l0;
        if (l1 > bv) { bv = l1; best = 1; }
        if (l2 > bv) { bv = l2; best = 2; }
        if (l3 > bv) { bv = l3; best = 3; }
        s_top = best;
    }
    __syncthreads();

    float Q = ori[s_top][c];
    ysh[c] = fmaxf(LL - Q, 0.f) + fmaxf(HL - Q, 0.f)
           + fmaxf(LH - Q, 0.f) + fmaxf(HHb - Q, 0.f);
    __syncthreads();

    if (c < CHAN / 2) {
        const float* __restrict__ row = w1 + (size_t)c * CHAN;
        float acc = 0.f;
        #pragma unroll 8
        for (int k = 0; k < CHAN; k++) acc = fmaf(ysh[k], row[k], acc);
        hsh[c] = fmaxf(acc, 0.f);
    }
    __syncthreads();

    {
        const float* __restrict__ row = w2 + (size_t)c * (CHAN / 2);
        float acc = 0.f;
        #pragma unroll 8
        for (int k = 0; k < CHAN / 2; k++) acc = fmaf(hsh[k], row[k], acc);
        g_scale[b * CHAN + c] = 1.0f / (1.0f + __expf(-acc));
        __threadfence();
    }
    __syncthreads();
    // publish: flag = 256*(run+1) = old+1 (monotonic, never reset)
    if (t == 0) atomicExch(&g_flag[b], old + 1u);
}

// ---------------------------------------------------------------------------
// K2 (PDL secondary): out = x * s. Issues its 7 independent x-loads BEFORE
// the flag wait (x is read-only). Run index derived from a monotonic
// per-batch counter — no reset kernel needed.
// ---------------------------------------------------------------------------
__global__ __launch_bounds__(256) void scale_kernel(const float* __restrict__ x,
                                                    float* __restrict__ out) {
    const int b = blockIdx.x / NSCB_PER_BATCH;
    const int inner = blockIdx.x % NSCB_PER_BATCH;
    const int plane = b * CHAN + inner / SBLK_PER_PLANE;
    const size_t base = (size_t)blockIdx.x * SBLK_V4 + threadIdx.x;

    const float4* __restrict__ src = (const float4*)x;
    float4* __restrict__ dst = (float4*)out;

    float4 v[V4_PER_THREAD];
    #pragma unroll
    for (int k = 0; k < V4_PER_THREAD; k++)
        v[k] = src[base + (size_t)k * 256];

    if (threadIdx.x == 0) {
        unsigned old = atomicAdd(&g_k2[b], 1u);
        unsigned target = (old / NSCB_PER_BATCH + 1u) * 256u;
        while (atomicAdd(&g_flag[b], 0u) < target) __nanosleep(64);
    }
    __syncthreads();
    const float s = __ldcg(&g_scale[plane]);

    #pragma unroll
    for (int k = 0; k < V4_PER_THREAD; k++) {
        v[k].x *= s; v[k].y *= s; v[k].z *= s; v[k].w *= s;
        __stcs(&dst[base + (size_t)k * 256], v[k]);
    }
}

// ---------------------------------------------------------------------------
extern "C" void kernel_launch(void* const* d_in, const int* in_sizes, int n_in,
                              void* d_out, int out_size) {
    const float* x     = (const float*)d_in[0];  // [16,256,224,224]
    const float* w1    = (const float*)d_in[1];  // [128,256]
    const float* w2    = (const float*)d_in[2];  // [256,128]
    const float* w_enc = (const float*)d_in[3];  // [1,256]
    float* out = (float*)d_out;

    sum_head_kernel<<<NPLANES, 256>>>(x, w1, w2, w_enc);

    // K2 as PDL secondary
    cudaLaunchConfig_t cfg = {};
    cfg.gridDim  = dim3(NSCB, 1, 1);
    cfg.blockDim = dim3(256, 1, 1);
    cfg.dynamicSmemBytes = 0;
    cudaLaunchAttribute attr[1];
    attr[0].id = cudaLaunchAttributeProgrammaticStreamSerialization;
    attr[0].val.programmaticStreamSerializationAllowed = 1;
    cfg.attrs = attr;
    cfg.numAttrs = 1;
    cudaLaunchKernelEx(&cfg, scale_kernel, x, out);
}

// round 14
// speedup vs baseline: 1.9786x; 1.0137x over previous
#include <cuda_runtime.h>
#include <cuda_bf16.h>
#include <math.h>

// Shapes (fixed by the problem)
#define BATCH 16
#define CHAN  256
#define HH_   224
#define WW_   224
#define PLANE_ELEMS (HH_ * WW_)          // 50176 floats per plane
#define PLANE_V4    (PLANE_ELEMS / 4)    // 12544 float4 per plane
#define NPLANES     (BATCH * CHAN)       // 4096
#define W4_PER_ROW  (WW_ / 4)            // 56 float4 per row
#define SUB_ELEMS   (112 * 112)

// K2 tiling: 448 threads, 7 float4/thread -> 3136 float4 = quarter plane.
#define K2_THREADS 448
#define V4_PER_THREAD 7
#define SBLK_V4 (K2_THREADS * V4_PER_THREAD)   // 3136 float4 per block
#define SBLK_PER_PLANE 4                        // 12544 / 3136
#define NSCB_PER_BATCH (CHAN * SBLK_PER_PLANE)  // 1024 blocks per batch
#define NSCB (BATCH * NSCB_PER_BATCH)           // 16384

// Scratch globals — all counters MONOTONIC (never reset): no init kernel.
__device__ float    g_sums[NPLANES * 4];
__device__ float    g_scale[NPLANES];
__device__ unsigned g_done[BATCH];   // K1 arrivals per batch (256 per run)
__device__ unsigned g_flag[BATCH];   // head publishes 256*(run+1)
__device__ unsigned g_k2[BATCH];     // K2 arrivals per batch (1024 per run)

// ---------------------------------------------------------------------------
// K1: parity sums (one block per plane) + inline head on the last block of
// each batch. griddepcontrol.launch_dependents at entry: K2 CTAs only fill
// slots K1 has freed — cannot starve K1.
// ---------------------------------------------------------------------------
__global__ __launch_bounds__(256) void sum_head_kernel(
        const float* __restrict__ x,
        const float* __restrict__ w1, const float* __restrict__ w2,
        const float* __restrict__ w_enc) {
    asm volatile("griddepcontrol.launch_dependents;" ::: "memory");

    const int plane = blockIdx.x;
    const int b = plane >> 8;
    const int t = threadIdx.x;
    const float4* __restrict__ p = (const float4*)x + (size_t)plane * PLANE_V4;

    float a0 = 0.f, a1 = 0.f, a2 = 0.f, a3 = 0.f;
    #pragma unroll 7
    for (int i = t; i < PLANE_V4; i += 256) {
        float4 v = p[i];
        int h = i / W4_PER_ROW;
        float ev = v.x + v.z;
        float od = v.y + v.w;
        if (h & 1) { a1 += ev; a3 += od; }
        else       { a0 += ev; a2 += od; }
    }
    #pragma unroll
    for (int off = 16; off > 0; off >>= 1) {
        a0 += __shfl_down_sync(0xffffffffu, a0, off);
        a1 += __shfl_down_sync(0xffffffffu, a1, off);
        a2 += __shfl_down_sync(0xffffffffu, a2, off);
        a3 += __shfl_down_sync(0xffffffffu, a3, off);
    }

    __shared__ float red[8][4];
    __shared__ unsigned s_old;
    int lane = t & 31, wid = t >> 5;
    if (lane == 0) { red[wid][0] = a0; red[wid][1] = a1; red[wid][2] = a2; red[wid][3] = a3; }
    __syncthreads();
    if (t < 4) {
        float acc = 0.f;
        #pragma unroll
        for (int w = 0; w < 8; w++) acc += red[w][t];
        g_sums[(size_t)plane * 4 + t] = acc;
        __threadfence();
    }
    __syncthreads();
    if (t == 0) s_old = atomicAdd(&g_done[b], 1u);
    __syncthreads();
    const unsigned old = s_old;
    if ((old & 255u) != 255u) return;   // not last block of this batch/run

    // ---- last block of batch b this run: inline head ----
    __shared__ float ori[4][CHAN];
    __shared__ float ysh[CHAN];
    __shared__ float hsh[CHAN / 2];
    __shared__ float rr[8][4];
    __shared__ int s_top;

    const int c = t;
    const float inv = 0.5f / (float)SUB_ELEMS;
    const size_t gi = ((size_t)b * CHAN + c) * 4;
    float m1 = __ldcg(&g_sums[gi + 0]) * inv;
    float m2 = __ldcg(&g_sums[gi + 1]) * inv;
    float m3 = __ldcg(&g_sums[gi + 2]) * inv;
    float m4 = __ldcg(&g_sums[gi + 3]) * inv;

    float LL  =  m1 + m2 + m3 + m4;
    float HL  = -m1 - m2 + m3 + m4;
    float LH  = -m1 + m2 - m3 + m4;
    float HHb =  m1 - m2 - m3 + m4;
    ori[0][c] = LL; ori[1][c] = HL; ori[2][c] = LH; ori[3][c] = HHb;

    float we = w_enc[c];
    float p0 = LL * we, p1 = HL * we, p2 = LH * we, p3 = HHb * we;
    #pragma unroll
    for (int off = 16; off > 0; off >>= 1) {
        p0 += __shfl_down_sync(0xffffffffu, p0, off);
        p1 += __shfl_down_sync(0xffffffffu, p1, off);
        p2 += __shfl_down_sync(0xffffffffu, p2, off);
        p3 += __shfl_down_sync(0xffffffffu, p3, off);
    }
    if (lane == 0) { rr[wid][0] = p0; rr[wid][1] = p1; rr[wid][2] = p2; rr[wid][3] = p3; }
    __syncthreads();
    if (t == 0) {
        float l0 = 0.f, l1 = 0.f, l2 = 0.f, l3 = 0.f;
        #pragma unroll
        for (int w = 0; w < 8; w++) { l0 += rr[w][0]; l1 += rr[w][1]; l2 += rr[w][2]; l3 += rr[w][3]; }
        int best = 0; float bv = l0;
        if (l1 > bv) { bv = l1; best = 1; }
        if (l2 > bv) { bv = l2; best = 2; }
        if (l3 > bv) { bv = l3; best = 3; }
        s_top = best;
    }
    __syncthreads();

    float Q = ori[s_top][c];
    ysh[c] = fmaxf(LL - Q, 0.f) + fmaxf(HL - Q, 0.f)
           + fmaxf(LH - Q, 0.f) + fmaxf(HHb - Q, 0.f);
    __syncthreads();

    if (c < CHAN / 2) {
        const float* __restrict__ row = w1 + (size_t)c * CHAN;
        float acc = 0.f;
        #pragma unroll 8
        for (int k = 0; k < CHAN; k++) acc = fmaf(ysh[k], row[k], acc);
        hsh[c] = fmaxf(acc, 0.f);
    }
    __syncthreads();

    {
        const float* __restrict__ row = w2 + (size_t)c * (CHAN / 2);
        float acc = 0.f;
        #pragma unroll 8
        for (int k = 0; k < CHAN / 2; k++) acc = fmaf(hsh[k], row[k], acc);
        g_scale[b * CHAN + c] = 1.0f / (1.0f + __expf(-acc));
        __threadfence();
    }
    __syncthreads();
    if (t == 0) atomicExch(&g_flag[b], old + 1u);  // = 256*(run+1), monotonic
}

// ---------------------------------------------------------------------------
// K2 (PDL secondary): out = x * s. 448 threads x 7 float4 -> 50 KB read
// burst, syncthreads, 50 KB write burst (block-wide phase separation reduces
// DRAM read/write turnarounds). Loads issued BEFORE the flag wait.
// ---------------------------------------------------------------------------
__global__ __launch_bounds__(K2_THREADS) void scale_kernel(
        const float* __restrict__ x, float* __restrict__ out) {
    const int b = blockIdx.x / NSCB_PER_BATCH;
    const int plane = blockIdx.x / SBLK_PER_PLANE;
    const size_t base = (size_t)blockIdx.x * SBLK_V4 + threadIdx.x;

    const float4* __restrict__ src = (const float4*)x;
    float4* __restrict__ dst = (float4*)out;

    float4 v[V4_PER_THREAD];
    #pragma unroll
    for (int k = 0; k < V4_PER_THREAD; k++)
        v[k] = src[base + (size_t)k * K2_THREADS];

    if (threadIdx.x == 0) {
        unsigned old = atomicAdd(&g_k2[b], 1u);
        unsigned target = (old / NSCB_PER_BATCH + 1u) * 256u;
        while (atomicAdd(&g_flag[b], 0u) < target) __nanosleep(64);
    }
    __syncthreads();
    const float s = __ldcg(&g_scale[plane]);

    #pragma unroll
    for (int k = 0; k < V4_PER_THREAD; k++) {
        v[k].x *= s; v[k].y *= s; v[k].z *= s; v[k].w *= s;
        __stcs(&dst[base + (size_t)k * K2_THREADS], v[k]);
    }
}

// ---------------------------------------------------------------------------
extern "C" void kernel_launch(void* const* d_in, const int* in_sizes, int n_in,
                              void* d_out, int out_size) {
    const float* x     = (const float*)d_in[0];  // [16,256,224,224]
    const float* w1    = (const float*)d_in[1];  // [128,256]
    const float* w2    = (const float*)d_in[2];  // [256,128]
    const float* w_enc = (const float*)d_in[3];  // [1,256]
    float* out = (float*)d_out;

    sum_head_kernel<<<NPLANES, 256>>>(x, w1, w2, w_enc);

    // K2 as PDL secondary
    cudaLaunchConfig_t cfg = {};
    cfg.gridDim  = dim3(NSCB, 1, 1);
    cfg.blockDim = dim3(K2_THREADS, 1, 1);
    cfg.dynamicSmemBytes = 0;
    cudaLaunchAttribute attr[1];
    attr[0].id = cudaLaunchAttributeProgrammaticStreamSerialization;
    attr[0].val.programmaticStreamSerializationAllowed = 1;
    cfg.attrs = attr;
    cfg.numAttrs = 1;
    cudaLaunchKernelEx(&cfg, scale_kernel, x, out);
}